// round 9
// baseline (speedup 1.0000x reference)
#include <cuda_runtime.h>
#include <cuda_fp16.h>

// DistMult scoring, R8: two-pass fp16.
//   pass 1: Ah = fp16(A * k), Bh = fp16(B)  (streaming __ldcs reads protect
//           the L2-pinned fp16 tables; 16B evict_last stores)
//   pass 2: gather-dot scoring, 8 lanes per edge (4 edges/warp): reduction
//           cost ~4.8 shfl/edge, loads coalesced 256B/row, cp.async staging.
// out = [pos (E), head (4E), tail (4E)]

#define D 128
#define NEG 4
#define WPB 4            // warps per block (score kernel)
#define EPB (4 * WPB)    // edges per block (4 per warp)
#define NROWS 100000

__device__ __align__(16) __half d_Ah[(size_t)NROWS * D];
__device__ __align__(16) __half d_Bh[(size_t)NROWS * D];

__device__ __forceinline__ unsigned h2_bits(__half2 h) {
    return *reinterpret_cast<unsigned*>(&h);
}

// fp32 result of an 8-element fp16 dot; two half2 chains.
__device__ __forceinline__ float dot_h8(uint4 x, uint4 y) {
    const __half2* xa = (const __half2*)&x;
    const __half2* ya = (const __half2*)&y;
    __half2 acc0 = __hmul2(xa[0], ya[0]);
    __half2 acc1 = __hmul2(xa[1], ya[1]);
    acc0 = __hfma2(xa[2], ya[2], acc0);
    acc1 = __hfma2(xa[3], ya[3], acc1);
    acc0 = __hadd2(acc0, acc1);
    return __low2float(acc0) + __high2float(acc0);
}

// 16B register load, L1 non-coherent, L2 evict_last
__device__ __forceinline__ uint4 ldg_resident_u4(const uint4* p, unsigned long long pol) {
    uint4 r;
    asm volatile(
        "ld.global.nc.L2::cache_hint.v4.u32 {%0,%1,%2,%3}, [%4], %5;"
        : "=r"(r.x), "=r"(r.y), "=r"(r.z), "=r"(r.w)
        : "l"(p), "l"(pol));
    return r;
}

// 16B async copy global->shared, bypass L1, L2 evict_last
__device__ __forceinline__ void cp_async16(unsigned smem_dst, const void* gptr,
                                           unsigned long long pol) {
    asm volatile(
        "cp.async.cg.shared.global.L2::cache_hint [%0], [%1], 16, %2;"
        :: "r"(smem_dst), "l"(gptr), "l"(pol));
}

// ---------------- pass 1: fp32 -> fp16 conversion -----------------------
// one thread per 8 floats; streaming reads (evict_first), evict_last stores.
__global__ void __launch_bounds__(256) convert_kernel(
    const float4* __restrict__ A4,
    const float4* __restrict__ B4,
    const float*  __restrict__ K,
    int nA8, int nB8)
{
    int i = blockIdx.x * blockDim.x + threadIdx.x;

    unsigned long long pol;  // keep fp16 tables L2-resident
    asm volatile("createpolicy.fractional.L2::evict_last.b64 %0, 1.0;" : "=l"(pol));

    if (i < nA8) {
        float4 v0 = __ldcs(A4 + 2 * (size_t)i);
        float4 v1 = __ldcs(A4 + 2 * (size_t)i + 1);
        float4 k0 = __ldg((const float4*)K + ((2 * i) & 31));
        float4 k1 = __ldg((const float4*)K + ((2 * i + 1) & 31));
        __half2 h0 = __floats2half2_rn(v0.x * k0.x, v0.y * k0.y);
        __half2 h1 = __floats2half2_rn(v0.z * k0.z, v0.w * k0.w);
        __half2 h2 = __floats2half2_rn(v1.x * k1.x, v1.y * k1.y);
        __half2 h3 = __floats2half2_rn(v1.z * k1.z, v1.w * k1.w);
        unsigned u0 = h2_bits(h0), u1 = h2_bits(h1);
        unsigned u2 = h2_bits(h2), u3 = h2_bits(h3);
        uint4* dst = reinterpret_cast<uint4*>(d_Ah) + i;
        asm volatile("st.global.L2::cache_hint.v4.u32 [%0], {%1,%2,%3,%4}, %5;"
                     :: "l"(dst), "r"(u0), "r"(u1), "r"(u2), "r"(u3), "l"(pol));
    } else if (i < nA8 + nB8) {
        int j = i - nA8;
        float4 v0 = __ldcs(B4 + 2 * (size_t)j);
        float4 v1 = __ldcs(B4 + 2 * (size_t)j + 1);
        __half2 h0 = __floats2half2_rn(v0.x, v0.y);
        __half2 h1 = __floats2half2_rn(v0.z, v0.w);
        __half2 h2 = __floats2half2_rn(v1.x, v1.y);
        __half2 h3 = __floats2half2_rn(v1.z, v1.w);
        unsigned u0 = h2_bits(h0), u1 = h2_bits(h1);
        unsigned u2 = h2_bits(h2), u3 = h2_bits(h3);
        uint4* dst = reinterpret_cast<uint4*>(d_Bh) + j;
        asm volatile("st.global.L2::cache_hint.v4.u32 [%0], {%1,%2,%3,%4}, %5;"
                     :: "l"(dst), "r"(u0), "r"(u1), "r"(u2), "r"(u3), "l"(pol));
    }
}

// ---------------- pass 2: gather-dot scoring ----------------------------
// 8 lanes per edge; lane l3 (0-7) owns uint4 slots {2*l3, 2*l3+1} of each
// 16-uint4 (256B) fp16 row.
__global__ void __launch_bounds__(32 * WPB) score_kernel(
    const int* __restrict__ ep,    // [2, E]
    const int* __restrict__ hb,    // [E, 4]
    const int* __restrict__ tb,    // [E, 4]
    float*     __restrict__ out,   // [9E]
    int E)
{
    // per edge-group: 8 corrupt rows x 256B = 2KB
    __shared__ uint4 sbuf[EPB][2 * NEG][16];
    __shared__ float sout[EPB][9];

    int g   = threadIdx.x >> 3;      // group (edge slot) within block, 0..EPB-1
    int l3  = threadIdx.x & 7;       // lane within group
    int e   = blockIdx.x * EPB + g;

    unsigned long long pol;
    asm volatile("createpolicy.fractional.L2::evict_last.b64 %0, 1.0;" : "=l"(pol));

    if (e < E) {
        int h = __ldg(&ep[e]);
        int t = __ldg(&ep[E + e]);
        int4 hbi = __ldg((const int4*)(hb) + e);
        int4 tbi = __ldg((const int4*)(tb) + e);
        int hidx[NEG] = {hbi.x, hbi.y, hbi.z, hbi.w};
        int tidx[NEG] = {tbi.x, tbi.y, tbi.z, tbi.w};

        const uint4* Ah4 = (const uint4*)d_Ah;  // 16 uint4 per row
        const uint4* Bh4 = (const uint4*)d_Bh;

        // stage 8 corrupt rows: each lane copies its own 32B slice of each row
        unsigned s0 = (unsigned)__cvta_generic_to_shared(&sbuf[g][0][2 * l3]);
#pragma unroll
        for (int j = 0; j < NEG; j++) {
            const uint4* hrow = Ah4 + (size_t)hidx[j] * (D / 8) + 2 * l3;
            cp_async16(s0 + (unsigned)j * 256u,       hrow, pol);
            cp_async16(s0 + (unsigned)j * 256u + 16u, hrow + 1, pol);
        }
#pragma unroll
        for (int j = 0; j < NEG; j++) {
            const uint4* trow = Bh4 + (size_t)tidx[j] * (D / 8) + 2 * l3;
            cp_async16(s0 + (unsigned)(NEG + j) * 256u,       trow, pol);
            cp_async16(s0 + (unsigned)(NEG + j) * 256u + 16u, trow + 1, pol);
        }
        asm volatile("cp.async.commit_group;");

        // positive rows (k folded into Ah)
        uint4 av0 = ldg_resident_u4(Ah4 + (size_t)h * (D / 8) + 2 * l3, pol);
        uint4 av1 = ldg_resident_u4(Ah4 + (size_t)h * (D / 8) + 2 * l3 + 1, pol);
        uint4 bv0 = ldg_resident_u4(Bh4 + (size_t)t * (D / 8) + 2 * l3, pol);
        uint4 bv1 = ldg_resident_u4(Bh4 + (size_t)t * (D / 8) + 2 * l3 + 1, pol);
        float pos = dot_h8(av0, bv0) + dot_h8(av1, bv1);

        asm volatile("cp.async.wait_group 0;");

        float hs[NEG], ts[NEG];
#pragma unroll
        for (int j = 0; j < NEG; j++) {
            hs[j] = dot_h8(sbuf[g][j][2 * l3], bv0)
                  + dot_h8(sbuf[g][j][2 * l3 + 1], bv1);
            ts[j] = dot_h8(av0, sbuf[g][NEG + j][2 * l3])
                  + dot_h8(av1, sbuf[g][NEG + j][2 * l3 + 1]);
        }

        // --- packed reduction over the 8-lane group (xor masks < 8) ---
        pos += __shfl_xor_sync(0xFFFFFFFFu, pos, 4);
#pragma unroll
        for (int j = 0; j < NEG; j++) {
            hs[j] += __shfl_xor_sync(0xFFFFFFFFu, hs[j], 4);
            ts[j] += __shfl_xor_sync(0xFFFFFFFFu, ts[j], 4);
        }
        bool hi = (l3 & 4) != 0;
        float r0 = hi ? hs[0] : pos;
        float r1 = hi ? hs[2] : hs[1];
        float r2 = hi ? ts[0] : hs[3];
        float r3 = hi ? ts[2] : ts[1];
        float r4 = ts[3];
#pragma unroll
        for (int m = 2; m >= 1; m >>= 1) {
            r0 += __shfl_xor_sync(0xFFFFFFFFu, r0, m);
            r1 += __shfl_xor_sync(0xFFFFFFFFu, r1, m);
            r2 += __shfl_xor_sync(0xFFFFFFFFu, r2, m);
            r3 += __shfl_xor_sync(0xFFFFFFFFu, r3, m);
            r4 += __shfl_xor_sync(0xFFFFFFFFu, r4, m);
        }

        // routing: lo lanes 0-3 -> {pos,hs1,hs3,ts1} = idx {0,2,4,6}
        //          hi lanes 4-7 -> {hs0,hs2,ts0,ts2} = idx {1,3,5,7}
        //          lane 0 also writes ts3 (idx 8)
        int q = l3 & 3;
        float val = (q == 0) ? r0 : (q == 1) ? r1 : (q == 2) ? r2 : r3;
        int idx = 2 * q + (l3 >> 2);
        sout[g][idx] = val;
        if (l3 == 0) sout[g][8] = r4;
    }
    __syncthreads();

    // coalesced block-level stores
    int e0 = blockIdx.x * EPB;
    int nb = E - e0; if (nb > EPB) nb = EPB;
    if (nb > 0) {
        int t = threadIdx.x;
        if (t < nb)
            __stcs(&out[e0 + t], sout[t][0]);
        if (t < nb * NEG) {
            int we = t >> 2, j = t & 3;
            __stcs(&out[(size_t)E + (size_t)e0 * NEG + t], sout[we][1 + j]);
            __stcs(&out[(size_t)E * (1 + NEG) + (size_t)e0 * NEG + t], sout[we][5 + j]);
        }
    }
}

extern "C" void kernel_launch(void* const* d_in, const int* in_sizes, int n_in,
                              void* d_out, int out_size) {
    const float* emb_A = (const float*)d_in[0];
    const float* emb_B = (const float*)d_in[1];
    const float* rel_k = (const float*)d_in[2];
    const int*   ep    = (const int*)d_in[3];
    const int*   hb    = (const int*)d_in[4];
    const int*   tb    = (const int*)d_in[5];
    float*       out   = (float*)d_out;

    int E   = in_sizes[3] / 2;
    int nA8 = in_sizes[0] / 8;
    int nB8 = in_sizes[1] / 8;

    int ntot = nA8 + nB8;
    convert_kernel<<<(ntot + 255) / 256, 256>>>(
        (const float4*)emb_A, (const float4*)emb_B, rel_k, nA8, nB8);

    int grid = (E + EPB - 1) / EPB;
    score_kernel<<<grid, 32 * WPB>>>(ep, hb, tb, out, E);
}

// round 10
// speedup vs baseline: 1.2049x; 1.2049x over previous
#include <cuda_runtime.h>
#include <cuda_fp16.h>

// DistMult scoring, R9 = best halves of R7/R8:
//   pass 1 (R8): Ah = fp16(A*k), Bh = fp16(B); __ldcs streaming reads protect
//                the L2-pinned fp16 tables; 16B evict_last stores. ~15 us.
//   pass 2 (R7): 2 edges/warp, 16 lanes/edge, cp.async staging, HFMA2 dots,
//                packed butterfly reduction. sout aliased into sbuf -> 32KB
//                smem exactly -> 7 blocks/SM (was 6).
// out = [pos (E), head (4E), tail (4E)]

#define D 128
#define NEG 4
#define WPB 8            // warps per block (score kernel)
#define EPB (2 * WPB)    // edges per block
#define NROWS 100000

__device__ __align__(16) __half d_Ah[(size_t)NROWS * D];
__device__ __align__(16) __half d_Bh[(size_t)NROWS * D];

__device__ __forceinline__ unsigned h2_bits(__half2 h) {
    return *reinterpret_cast<unsigned*>(&h);
}

// fp32 result of an 8-element fp16 dot; two half2 chains.
__device__ __forceinline__ float dot_h8(uint4 x, uint4 y) {
    const __half2* xa = (const __half2*)&x;
    const __half2* ya = (const __half2*)&y;
    __half2 acc0 = __hmul2(xa[0], ya[0]);
    __half2 acc1 = __hmul2(xa[1], ya[1]);
    acc0 = __hfma2(xa[2], ya[2], acc0);
    acc1 = __hfma2(xa[3], ya[3], acc1);
    acc0 = __hadd2(acc0, acc1);
    return __low2float(acc0) + __high2float(acc0);
}

// 16B register load, L1 non-coherent, L2 evict_last
__device__ __forceinline__ uint4 ldg_resident_u4(const uint4* p, unsigned long long pol) {
    uint4 r;
    asm volatile(
        "ld.global.nc.L2::cache_hint.v4.u32 {%0,%1,%2,%3}, [%4], %5;"
        : "=r"(r.x), "=r"(r.y), "=r"(r.z), "=r"(r.w)
        : "l"(p), "l"(pol));
    return r;
}

// 16B async copy global->shared, bypass L1, L2 evict_last
__device__ __forceinline__ void cp_async16(unsigned smem_dst, const void* gptr,
                                           unsigned long long pol) {
    asm volatile(
        "cp.async.cg.shared.global.L2::cache_hint [%0], [%1], 16, %2;"
        :: "r"(smem_dst), "l"(gptr), "l"(pol));
}

// ---------------- pass 1: fp32 -> fp16 conversion -----------------------
__global__ void __launch_bounds__(256) convert_kernel(
    const float4* __restrict__ A4,
    const float4* __restrict__ B4,
    const float*  __restrict__ K,
    int nA8, int nB8)
{
    int i = blockIdx.x * blockDim.x + threadIdx.x;

    unsigned long long pol;  // keep fp16 tables L2-resident
    asm volatile("createpolicy.fractional.L2::evict_last.b64 %0, 1.0;" : "=l"(pol));

    if (i < nA8) {
        float4 v0 = __ldcs(A4 + 2 * (size_t)i);
        float4 v1 = __ldcs(A4 + 2 * (size_t)i + 1);
        float4 k0 = __ldg((const float4*)K + ((2 * i) & 31));
        float4 k1 = __ldg((const float4*)K + ((2 * i + 1) & 31));
        __half2 h0 = __floats2half2_rn(v0.x * k0.x, v0.y * k0.y);
        __half2 h1 = __floats2half2_rn(v0.z * k0.z, v0.w * k0.w);
        __half2 h2 = __floats2half2_rn(v1.x * k1.x, v1.y * k1.y);
        __half2 h3 = __floats2half2_rn(v1.z * k1.z, v1.w * k1.w);
        unsigned u0 = h2_bits(h0), u1 = h2_bits(h1);
        unsigned u2 = h2_bits(h2), u3 = h2_bits(h3);
        uint4* dst = reinterpret_cast<uint4*>(d_Ah) + i;
        asm volatile("st.global.L2::cache_hint.v4.u32 [%0], {%1,%2,%3,%4}, %5;"
                     :: "l"(dst), "r"(u0), "r"(u1), "r"(u2), "r"(u3), "l"(pol));
    } else if (i < nA8 + nB8) {
        int j = i - nA8;
        float4 v0 = __ldcs(B4 + 2 * (size_t)j);
        float4 v1 = __ldcs(B4 + 2 * (size_t)j + 1);
        __half2 h0 = __floats2half2_rn(v0.x, v0.y);
        __half2 h1 = __floats2half2_rn(v0.z, v0.w);
        __half2 h2 = __floats2half2_rn(v1.x, v1.y);
        __half2 h3 = __floats2half2_rn(v1.z, v1.w);
        unsigned u0 = h2_bits(h0), u1 = h2_bits(h1);
        unsigned u2 = h2_bits(h2), u3 = h2_bits(h3);
        uint4* dst = reinterpret_cast<uint4*>(d_Bh) + j;
        asm volatile("st.global.L2::cache_hint.v4.u32 [%0], {%1,%2,%3,%4}, %5;"
                     :: "l"(dst), "r"(u0), "r"(u1), "r"(u2), "r"(u3), "l"(pol));
    }
}

// ---------------- pass 2: gather-dot scoring ----------------------------
__global__ void __launch_bounds__(32 * WPB) score_kernel(
    const int* __restrict__ ep,    // [2, E]
    const int* __restrict__ hb,    // [E, 4]
    const int* __restrict__ tb,    // [E, 4]
    float*     __restrict__ out,   // [9E]
    int E)
{
    // 32 KB staging; per-warp result floats (2 edges x 9) are aliased into the
    // warp's own staging region (written strictly after its last sbuf read,
    // read by the epilogue after __syncthreads).
    __shared__ uint4 sbuf[WPB][2 * NEG][32];
#define SOUT(g, idx) (((float*)&sbuf[(g) >> 1][0][0])[((g) & 1) * 9 + (idx)])

    int w     = threadIdx.x >> 5;
    int lane  = threadIdx.x & 31;
    int laneh = lane & 15;
    int side  = lane >> 4;
    int e     = 2 * (blockIdx.x * WPB + w) + side;

    unsigned long long pol;
    asm volatile("createpolicy.fractional.L2::evict_last.b64 %0, 1.0;" : "=l"(pol));

    if (e < E) {
        int h = __ldg(&ep[e]);
        int t = __ldg(&ep[E + e]);
        int4 hbi = __ldg((const int4*)(hb) + e);
        int4 tbi = __ldg((const int4*)(tb) + e);
        int hidx[NEG] = {hbi.x, hbi.y, hbi.z, hbi.w};
        int tidx[NEG] = {tbi.x, tbi.y, tbi.z, tbi.w};

        const uint4* Ah4 = (const uint4*)d_Ah;  // 16 uint4 per 128-half row
        const uint4* Bh4 = (const uint4*)d_Bh;

        unsigned s0 = (unsigned)__cvta_generic_to_shared(&sbuf[w][0][lane]);
#pragma unroll
        for (int j = 0; j < NEG; j++)
            cp_async16(s0 + (unsigned)j * 512u,
                       Ah4 + (size_t)hidx[j] * (D / 8) + laneh, pol);
#pragma unroll
        for (int j = 0; j < NEG; j++)
            cp_async16(s0 + (unsigned)(NEG + j) * 512u,
                       Bh4 + (size_t)tidx[j] * (D / 8) + laneh, pol);
        asm volatile("cp.async.commit_group;");

        // positive rows (k already folded into Ah)
        uint4 av = ldg_resident_u4(Ah4 + (size_t)h * (D / 8) + laneh, pol);
        uint4 bv = ldg_resident_u4(Bh4 + (size_t)t * (D / 8) + laneh, pol);
        float pos = dot_h8(av, bv);

        asm volatile("cp.async.wait_group 0;");

        float hs[NEG], ts[NEG];
#pragma unroll
        for (int j = 0; j < NEG; j++) {
            hs[j] = dot_h8(sbuf[w][j][lane], bv);
            ts[j] = dot_h8(av, sbuf[w][NEG + j][lane]);
        }

        // --- packed butterfly reduction over the 16-lane half ---
        pos += __shfl_xor_sync(0xFFFFFFFFu, pos, 8);
#pragma unroll
        for (int j = 0; j < NEG; j++) {
            hs[j] += __shfl_xor_sync(0xFFFFFFFFu, hs[j], 8);
            ts[j] += __shfl_xor_sync(0xFFFFFFFFu, ts[j], 8);
        }
        bool hi = laneh >= 8;
        float r0 = hi ? hs[0] : pos;
        float r1 = hi ? hs[2] : hs[1];
        float r2 = hi ? ts[0] : hs[3];
        float r3 = hi ? ts[2] : ts[1];
        float r4 = ts[3];
#pragma unroll
        for (int m = 4; m >= 1; m >>= 1) {
            r0 += __shfl_xor_sync(0xFFFFFFFFu, r0, m);
            r1 += __shfl_xor_sync(0xFFFFFFFFu, r1, m);
            r2 += __shfl_xor_sync(0xFFFFFFFFu, r2, m);
            r3 += __shfl_xor_sync(0xFFFFFFFFu, r3, m);
            r4 += __shfl_xor_sync(0xFFFFFFFFu, r4, m);
        }

        // laneh 0..4 hold {pos,hs1,hs3,ts1,ts3}; laneh 8..11 hold {hs0,hs2,ts0,ts2}
        int lh = laneh & 7;
        float val = r4;
        if (lh == 0) val = r0;
        else if (lh == 1) val = r1;
        else if (lh == 2) val = r2;
        else if (lh == 3) val = r3;
        int idx = 2 * lh + (laneh >> 3);
        bool active = hi ? (lh < 4) : (lh < 5);
        if (active) SOUT(2 * w + side, idx) = val;
        // idx: 0=pos, 1=hs0, 2=hs1, 3=hs2, 4=hs3, 5=ts0, 6=ts1, 7=ts2, 8=ts3
    }
    __syncthreads();

    // coalesced block-level stores
    int e0 = blockIdx.x * EPB;
    int nb = E - e0; if (nb > EPB) nb = EPB;
    if (nb > 0) {
        int t = threadIdx.x;
        if (t < nb)
            __stcs(&out[e0 + t], SOUT(t, 0));
        if (t < nb * NEG) {
            int we = t >> 2, j = t & 3;
            __stcs(&out[(size_t)E + (size_t)e0 * NEG + t], SOUT(we, 1 + j));
            __stcs(&out[(size_t)E * (1 + NEG) + (size_t)e0 * NEG + t], SOUT(we, 5 + j));
        }
    }
#undef SOUT
}

extern "C" void kernel_launch(void* const* d_in, const int* in_sizes, int n_in,
                              void* d_out, int out_size) {
    const float* emb_A = (const float*)d_in[0];
    const float* emb_B = (const float*)d_in[1];
    const float* rel_k = (const float*)d_in[2];
    const int*   ep    = (const int*)d_in[3];
    const int*   hb    = (const int*)d_in[4];
    const int*   tb    = (const int*)d_in[5];
    float*       out   = (float*)d_out;

    int E   = in_sizes[3] / 2;
    int nA8 = in_sizes[0] / 8;
    int nB8 = in_sizes[1] / 8;

    int ntot = nA8 + nB8;
    convert_kernel<<<(ntot + 255) / 256, 256>>>(
        (const float4*)emb_A, (const float4*)emb_B, rel_k, nA8, nB8);

    int grid = (E + EPB - 1) / EPB;
    score_kernel<<<grid, 32 * WPB>>>(ep, hb, tb, out, E);
}